// round 1
// baseline (speedup 1.0000x reference)
#include <cuda_runtime.h>

#define BATCH  4
#define SEQ    2048
#define DMODEL 768
#define NHEAD  12
#define HSZ    64
#define MROWS  (BATCH*SEQ)

// Scratch (alloc-free rule: __device__ globals). 4 x 25.2 MB.
__device__ float g_Q  [BATCH*NHEAD*SEQ*HSZ];
__device__ float g_K  [BATCH*NHEAD*SEQ*HSZ];
__device__ float g_V  [BATCH*NHEAD*SEQ*HSZ];
__device__ float g_Att[BATCH*NHEAD*SEQ*HSZ];

// ---------------------------------------------------------------------------
// Tiled SGEMM: Y[M,N] = X[M,K] @ W[N,K]^T + bias  (M=8192, N=K=768)
// MODE 0: plain X load, head-split permuted store (-> [B,H,S,d])
// MODE 1: head-merge gather load (<- [B,H,S,d]), plain store
// Block: 64x64 output tile, BK=16, 256 threads, 4x4 microtile per thread.
// ---------------------------------------------------------------------------
template<int MODE>
__global__ __launch_bounds__(256)
void gemm_kernel(const float* __restrict__ X, const float* __restrict__ W,
                 const float* __restrict__ bias, float* __restrict__ Y)
{
    __shared__ float Xs[16][65];
    __shared__ float Ws[16][65];
    const int m0  = blockIdx.y * 64;
    const int n0  = blockIdx.x * 64;
    const int tid = threadIdx.x;
    const int lrow = tid >> 2;          // 0..63
    const int lk4  = (tid & 3) << 2;    // 0,4,8,12
    const int ty = tid >> 4;            // 0..15
    const int tx = tid & 15;            // 0..15

    float acc[4][4];
#pragma unroll
    for (int i = 0; i < 4; i++)
#pragma unroll
        for (int j = 0; j < 4; j++) acc[i][j] = 0.f;

    for (int k0 = 0; k0 < DMODEL; k0 += 16) {
        float4 xv;
        if (MODE == 0) {
            xv = *(const float4*)(X + (size_t)(m0 + lrow) * DMODEL + k0 + lk4);
        } else {
            const int m = m0 + lrow;
            const int b = m >> 11, s = m & (SEQ - 1);
            const int k = k0 + lk4;
            const int h = k >> 6, dd = k & 63;
            xv = *(const float4*)(X + ((size_t)((b*NHEAD + h)*SEQ + s))*HSZ + dd);
        }
        Xs[lk4+0][lrow] = xv.x; Xs[lk4+1][lrow] = xv.y;
        Xs[lk4+2][lrow] = xv.z; Xs[lk4+3][lrow] = xv.w;

        float4 wv = *(const float4*)(W + (size_t)(n0 + lrow) * DMODEL + k0 + lk4);
        Ws[lk4+0][lrow] = wv.x; Ws[lk4+1][lrow] = wv.y;
        Ws[lk4+2][lrow] = wv.z; Ws[lk4+3][lrow] = wv.w;
        __syncthreads();

#pragma unroll
        for (int k = 0; k < 16; k++) {
            float a0 = Xs[k][ty*4+0], a1 = Xs[k][ty*4+1];
            float a2 = Xs[k][ty*4+2], a3 = Xs[k][ty*4+3];
            float b0 = Ws[k][tx*4+0], b1 = Ws[k][tx*4+1];
            float b2 = Ws[k][tx*4+2], b3 = Ws[k][tx*4+3];
            acc[0][0] += a0*b0; acc[0][1] += a0*b1; acc[0][2] += a0*b2; acc[0][3] += a0*b3;
            acc[1][0] += a1*b0; acc[1][1] += a1*b1; acc[1][2] += a1*b2; acc[1][3] += a1*b3;
            acc[2][0] += a2*b0; acc[2][1] += a2*b1; acc[2][2] += a2*b2; acc[2][3] += a2*b3;
            acc[3][0] += a3*b0; acc[3][1] += a3*b1; acc[3][2] += a3*b2; acc[3][3] += a3*b3;
        }
        __syncthreads();
    }

#pragma unroll
    for (int i = 0; i < 4; i++) {
        const int m = m0 + ty*4 + i;
#pragma unroll
        for (int j = 0; j < 4; j++) {
            const int n = n0 + tx*4 + j;
            const float v = acc[i][j] + bias[n];
            if (MODE == 0) {
                const int b = m >> 11, s = m & (SEQ - 1);
                const int h = n >> 6, dd = n & 63;
                Y[((size_t)((b*NHEAD + h)*SEQ + s))*HSZ + dd] = v;
            } else {
                Y[(size_t)m * DMODEL + n] = v;
            }
        }
    }
}

// ---------------------------------------------------------------------------
// Causal flash attention, fp32. One q-row per thread (q + O in registers),
// 128 q-rows per block, 64-wide K/V tiles in smem. Blocks only iterate
// k-tiles up to the causal diagonal.
// ---------------------------------------------------------------------------
__global__ __launch_bounds__(128)
void attn_kernel(const float* __restrict__ Q, const float* __restrict__ K,
                 const float* __restrict__ V, float* __restrict__ O)
{
    extern __shared__ float sm[];
    float (*Ks)[68] = (float (*)[68])(sm);
    float (*Vs)[68] = (float (*)[68])(sm + 64*68);
    float (*Ps)[65] = (float (*)[65])(sm + 2*64*68);

    const int bh  = blockIdx.y;              // b*H + h
    const int q0  = blockIdx.x * 128;
    const int tid = threadIdx.x;
    const int row = q0 + tid;                // global q row

    const float* Qb = Q + (size_t)bh * SEQ * HSZ;
    const float* Kb = K + (size_t)bh * SEQ * HSZ;
    const float* Vb = V + (size_t)bh * SEQ * HSZ;

    // pre-scale q by (1/sqrt(d)) * log2(e) so softmax uses exp2f
    const float scale = 0.125f * 1.44269504f;
    float4 q4[16];
#pragma unroll
    for (int i = 0; i < 16; i++) {
        float4 t = *(const float4*)(Qb + (size_t)row * HSZ + i*4);
        q4[i] = make_float4(t.x*scale, t.y*scale, t.z*scale, t.w*scale);
    }
    float4 o4[16];
#pragma unroll
    for (int i = 0; i < 16; i++) o4[i] = make_float4(0.f, 0.f, 0.f, 0.f);

    float mrow = -1e30f, lrow = 0.f;

    const int kend = q0 + 128;               // causal limit (exclusive)
    for (int kt = 0; kt < kend; kt += 64) {
        // cooperative K/V tile load (64 x 64 each), float4 per thread-iter
#pragma unroll
        for (int i = tid; i < 1024; i += 128) {
            const int r = i >> 4, c4 = (i & 15) << 2;
            *(float4*)&Ks[r][c4] = *(const float4*)(Kb + (size_t)(kt + r)*HSZ + c4);
            *(float4*)&Vs[r][c4] = *(const float4*)(Vb + (size_t)(kt + r)*HSZ + c4);
        }
        __syncthreads();

        // scores for this thread's row vs 64 keys (pairs of j for ILP)
        float tmax = -1e30f;
        for (int j = 0; j < 64; j += 2) {
            float4 a0 = make_float4(0.f,0.f,0.f,0.f);
            float4 a1 = make_float4(0.f,0.f,0.f,0.f);
#pragma unroll
            for (int k = 0; k < 16; k++) {
                float4 k0v = *(const float4*)&Ks[j  ][k*4];
                float4 k1v = *(const float4*)&Ks[j+1][k*4];
                a0.x += q4[k].x*k0v.x; a0.y += q4[k].y*k0v.y;
                a0.z += q4[k].z*k0v.z; a0.w += q4[k].w*k0v.w;
                a1.x += q4[k].x*k1v.x; a1.y += q4[k].y*k1v.y;
                a1.z += q4[k].z*k1v.z; a1.w += q4[k].w*k1v.w;
            }
            float s0 = (a0.x + a0.y) + (a0.z + a0.w);
            float s1 = (a1.x + a1.y) + (a1.z + a1.w);
            if (kt + j     > row) s0 = -1e30f;   // causal mask
            if (kt + j + 1 > row) s1 = -1e30f;
            Ps[tid][j]   = s0;
            Ps[tid][j+1] = s1;
            tmax = fmaxf(tmax, fmaxf(s0, s1));
        }

        // online softmax rescale
        const float mnew = fmaxf(mrow, tmax);
        const float corr = exp2f(mrow - mnew);
        lrow *= corr;
#pragma unroll
        for (int k = 0; k < 16; k++) {
            o4[k].x *= corr; o4[k].y *= corr; o4[k].z *= corr; o4[k].w *= corr;
        }

        float lsum = 0.f;
        for (int j = 0; j < 64; j++) {
            const float p = exp2f(Ps[tid][j] - mnew);
            lsum += p;
#pragma unroll
            for (int k = 0; k < 16; k++) {
                float4 vv = *(const float4*)&Vs[j][k*4];
                o4[k].x += p*vv.x; o4[k].y += p*vv.y;
                o4[k].z += p*vv.z; o4[k].w += p*vv.w;
            }
        }
        lrow += lsum;
        mrow  = mnew;
        __syncthreads();
    }

    const float inv = 1.0f / lrow;
    float* Ob = O + (size_t)bh * SEQ * HSZ + (size_t)row * HSZ;
#pragma unroll
    for (int k = 0; k < 16; k++) {
        float4 t = make_float4(o4[k].x*inv, o4[k].y*inv, o4[k].z*inv, o4[k].w*inv);
        *(float4*)(Ob + k*4) = t;
    }
}

// ---------------------------------------------------------------------------
extern "C" void kernel_launch(void* const* d_in, const int* in_sizes, int n_in,
                              void* d_out, int out_size)
{
    const float* queries = (const float*)d_in[0];
    const float* keys    = (const float*)d_in[1];
    const float* values  = (const float*)d_in[2];
    const float* W_Q = (const float*)d_in[3];
    const float* b_Q = (const float*)d_in[4];
    const float* W_K = (const float*)d_in[5];
    const float* b_K = (const float*)d_in[6];
    const float* W_V = (const float*)d_in[7];
    const float* b_V = (const float*)d_in[8];
    const float* W_O = (const float*)d_in[9];
    const float* b_O = (const float*)d_in[10];
    float* out = (float*)d_out;

    float *pQ, *pK, *pV, *pA;
    cudaGetSymbolAddress((void**)&pQ, g_Q);
    cudaGetSymbolAddress((void**)&pK, g_K);
    cudaGetSymbolAddress((void**)&pV, g_V);
    cudaGetSymbolAddress((void**)&pA, g_Att);

    dim3 gg(DMODEL/64, MROWS/64);   // (12, 128)
    gemm_kernel<0><<<gg, 256>>>(queries, W_Q, b_Q, pQ);
    gemm_kernel<0><<<gg, 256>>>(keys,    W_K, b_K, pK);
    gemm_kernel<0><<<gg, 256>>>(values,  W_V, b_V, pV);

    const int smem = (2*64*68 + 128*65) * (int)sizeof(float);  // 68096 B
    cudaFuncSetAttribute(attn_kernel,
                         cudaFuncAttributeMaxDynamicSharedMemorySize, smem);
    dim3 ga(SEQ/128, BATCH*NHEAD);  // (16, 48)
    attn_kernel<<<ga, 128, smem>>>(pQ, pK, pV, pA);

    gemm_kernel<1><<<gg, 256>>>(pA, W_O, b_O, out);
}

// round 3
// speedup vs baseline: 5.1971x; 5.1971x over previous
#include <cuda_runtime.h>
#include <cstdint>

#define BATCH  4
#define SEQ    2048
#define DMODEL 768
#define NHEAD  12
#define HSZ    64
#define MROWS  (BATCH*SEQ)

// Scratch (alloc-free rule). All [B,S,D] layout.
__device__ float g_Q  [MROWS*DMODEL];
__device__ float g_K  [MROWS*DMODEL];
__device__ float g_V  [MROWS*DMODEL];
__device__ float g_Ctx[MROWS*DMODEL];

__device__ __forceinline__ uint32_t f2tf32(float x) {
    uint32_t r; asm("cvt.rna.tf32.f32 %0, %1;" : "=r"(r) : "f"(x)); return r;
}
__device__ __forceinline__ float ex2(float x) {
    float r; asm("ex2.approx.ftz.f32 %0, %1;" : "=f"(r) : "f"(x)); return r;
}

// D += A(16x8,row) * B(8x8,col)   A,B tf32
#define MMA_TF32(d, a, b0v, b1v)                                               \
    asm volatile("mma.sync.aligned.m16n8k8.row.col.f32.tf32.tf32.f32 "         \
        "{%0,%1,%2,%3}, {%4,%5,%6,%7}, {%8,%9}, {%0,%1,%2,%3};"                \
        : "+f"((d)[0]), "+f"((d)[1]), "+f"((d)[2]), "+f"((d)[3])               \
        : "r"((a)[0]), "r"((a)[1]), "r"((a)[2]), "r"((a)[3]),                  \
          "r"(b0v), "r"(b1v))

// ---------------------------------------------------------------------------
// GEMM: Y[M,N] = X[M,K] @ W[N,K]^T + bias   (M=8192, N=K=768), tf32 mma.sync
// CTA 128x128, 8 warps in 2(M)x4(N), warp tile 64x32, K-chunk 32.
// smem tiles [128][36] (pad 36 words -> fragment LDS banks 4g+tg, all distinct)
// ---------------------------------------------------------------------------
#define GSTRIDE 36

__global__ __launch_bounds__(256)
void gemm_mma(const float* __restrict__ X, const float* __restrict__ W,
              const float* __restrict__ bias, float* __restrict__ Y)
{
    __shared__ uint32_t As[128 * GSTRIDE];
    __shared__ uint32_t Bs[128 * GSTRIDE];

    const int tid  = threadIdx.x;
    const int wid  = tid >> 5, lane = tid & 31;
    const int g    = lane >> 2, tg = lane & 3;
    const int m0   = blockIdx.y * 128, n0 = blockIdx.x * 128;
    const int wm   = (wid & 1) * 64;        // warp row base
    const int wn   = (wid >> 1) * 32;       // warp col base
    const int r_ld = tid >> 3;              // 0..31 (+32j)
    const int c_ld = tid & 7;               // float4 slot in 32-wide K

    float acc[4][4][4] = {};

    float4 ra[4], rb[4];
#pragma unroll
    for (int j = 0; j < 4; j++) {
        const int r = r_ld + j * 32;
        ra[j] = *(const float4*)(X + (size_t)(m0 + r) * DMODEL + c_ld * 4);
        rb[j] = *(const float4*)(W + (size_t)(n0 + r) * DMODEL + c_ld * 4);
    }

    for (int kt = 0; kt < DMODEL / 32; kt++) {
        __syncthreads();   // previous tile fully consumed
#pragma unroll
        for (int j = 0; j < 4; j++) {
            const int r = r_ld + j * 32;
            uint32_t* pa = &As[r * GSTRIDE + c_ld * 4];
            uint32_t* pb = &Bs[r * GSTRIDE + c_ld * 4];
            *(uint2*)(pa)     = make_uint2(f2tf32(ra[j].x), f2tf32(ra[j].y));
            *(uint2*)(pa + 2) = make_uint2(f2tf32(ra[j].z), f2tf32(ra[j].w));
            *(uint2*)(pb)     = make_uint2(f2tf32(rb[j].x), f2tf32(rb[j].y));
            *(uint2*)(pb + 2) = make_uint2(f2tf32(rb[j].z), f2tf32(rb[j].w));
        }
        if (kt + 1 < DMODEL / 32) {
            const int k0 = (kt + 1) * 32;
#pragma unroll
            for (int j = 0; j < 4; j++) {
                const int r = r_ld + j * 32;
                ra[j] = *(const float4*)(X + (size_t)(m0 + r) * DMODEL + k0 + c_ld * 4);
                rb[j] = *(const float4*)(W + (size_t)(n0 + r) * DMODEL + k0 + c_ld * 4);
            }
        }
        __syncthreads();

#pragma unroll
        for (int k8 = 0; k8 < 4; k8++) {
            uint32_t a[4][4], b[4][2];
#pragma unroll
            for (int mt = 0; mt < 4; mt++) {
                const int base = (wm + mt * 16 + g) * GSTRIDE + k8 * 8 + tg;
                a[mt][0] = As[base];
                a[mt][1] = As[base + 8 * GSTRIDE];
                a[mt][2] = As[base + 4];
                a[mt][3] = As[base + 8 * GSTRIDE + 4];
            }
#pragma unroll
            for (int nt = 0; nt < 4; nt++) {
                const int base = (wn + nt * 8 + g) * GSTRIDE + k8 * 8 + tg;
                b[nt][0] = Bs[base];
                b[nt][1] = Bs[base + 4];
            }
#pragma unroll
            for (int mt = 0; mt < 4; mt++)
#pragma unroll
                for (int nt = 0; nt < 4; nt++)
                    MMA_TF32(acc[mt][nt], a[mt], b[nt][0], b[nt][1]);
        }
    }

#pragma unroll
    for (int mt = 0; mt < 4; mt++) {
        const int row = m0 + wm + mt * 16 + g;
#pragma unroll
        for (int nt = 0; nt < 4; nt++) {
            const int col = n0 + wn + nt * 8 + 2 * tg;
            const float b0v = bias[col], b1v = bias[col + 1];
            *(float2*)&Y[(size_t)row * DMODEL + col] =
                make_float2(acc[mt][nt][0] + b0v, acc[mt][nt][1] + b1v);
            *(float2*)&Y[(size_t)(row + 8) * DMODEL + col] =
                make_float2(acc[mt][nt][2] + b0v, acc[mt][nt][3] + b1v);
        }
    }
}

// ---------------------------------------------------------------------------
// Tensor-core causal flash attention. CTA = 64 q rows, 4 warps x 16 rows.
// K tile [64][68] (banks 4g+tg), V tile [64][72] (banks 8tg+g),
// P tile [64][68]. All fragment LDS conflict-free.
// ---------------------------------------------------------------------------
#define KS_STRIDE 68
#define VS_STRIDE 72
#define PS_STRIDE 68
#define ATTN_SMEM ((64*KS_STRIDE + 64*VS_STRIDE + 64*PS_STRIDE) * 4)

__global__ __launch_bounds__(128)
void attn_mma(const float* __restrict__ Q, const float* __restrict__ K,
              const float* __restrict__ V, float* __restrict__ O)
{
    extern __shared__ uint32_t smu[];
    uint32_t* Ks = smu;
    uint32_t* Vs = smu + 64 * KS_STRIDE;
    uint32_t* Ps = smu + 64 * KS_STRIDE + 64 * VS_STRIDE;

    const int tid = threadIdx.x, wid = tid >> 5, lane = tid & 31;
    const int g = lane >> 2, tg = lane & 3;
    const int bh = blockIdx.y, b = bh / NHEAD, h = bh % NHEAD;
    const int q0 = blockIdx.x * 64;
    const int wslab = wid * 16;

    const float* Qp = Q + (size_t)b * SEQ * DMODEL + h * HSZ;
    const float* Kp = K + (size_t)b * SEQ * DMODEL + h * HSZ;
    const float* Vp = V + (size_t)b * SEQ * DMODEL + h * HSZ;

    const int row0 = q0 + wslab + g;    // seq index of this lane's row 0
    const int row1 = row0 + 8;

    const float qs = 0.125f * 1.44269504f;   // 1/sqrt(64) * log2(e)
    uint32_t qa[8][4];
#pragma unroll
    for (int k8 = 0; k8 < 8; k8++) {
        const int c = k8 * 8 + tg;
        qa[k8][0] = f2tf32(Qp[(size_t)row0 * DMODEL + c]     * qs);
        qa[k8][1] = f2tf32(Qp[(size_t)row1 * DMODEL + c]     * qs);
        qa[k8][2] = f2tf32(Qp[(size_t)row0 * DMODEL + c + 4] * qs);
        qa[k8][3] = f2tf32(Qp[(size_t)row1 * DMODEL + c + 4] * qs);
    }

    float o[8][4] = {};
    float m0v = -1e30f, m1v = -1e30f, l0 = 0.f, l1 = 0.f;

    for (int kt = 0; kt <= q0; kt += 64) {
        __syncthreads();   // previous tile fully consumed
        for (int i = tid; i < 1024; i += 128) {
            const int r = i >> 4, c4 = (i & 15) << 2;
            float4 kv = *(const float4*)(Kp + (size_t)(kt + r) * DMODEL + c4);
            uint32_t* pk = &Ks[r * KS_STRIDE + c4];
            *(uint2*)(pk)     = make_uint2(f2tf32(kv.x), f2tf32(kv.y));
            *(uint2*)(pk + 2) = make_uint2(f2tf32(kv.z), f2tf32(kv.w));
            float4 vv = *(const float4*)(Vp + (size_t)(kt + r) * DMODEL + c4);
            uint32_t* pv = &Vs[r * VS_STRIDE + c4];
            *(uint2*)(pv)     = make_uint2(f2tf32(vv.x), f2tf32(vv.y));
            *(uint2*)(pv + 2) = make_uint2(f2tf32(vv.z), f2tf32(vv.w));
        }
        __syncthreads();

        // S = Q @ K^T  (per warp: 16 rows x 64 keys)
        float s[8][4] = {};
#pragma unroll
        for (int k8 = 0; k8 < 8; k8++) {
#pragma unroll
            for (int nt = 0; nt < 8; nt++) {
                const int base = (nt * 8 + g) * KS_STRIDE + k8 * 8 + tg;
                MMA_TF32(s[nt], qa[k8], Ks[base], Ks[base + 4]);
            }
        }

        if (kt == q0) {   // diagonal tile: causal mask
#pragma unroll
            for (int nt = 0; nt < 8; nt++) {
                const int cl = kt + nt * 8 + 2 * tg;
                if (cl     > row0) s[nt][0] = -1e30f;
                if (cl + 1 > row0) s[nt][1] = -1e30f;
                if (cl     > row1) s[nt][2] = -1e30f;
                if (cl + 1 > row1) s[nt][3] = -1e30f;
            }
        }

        // row max (across lane cols, then across the 4 tg lanes)
        float mx0 = -1e30f, mx1 = -1e30f;
#pragma unroll
        for (int nt = 0; nt < 8; nt++) {
            mx0 = fmaxf(mx0, fmaxf(s[nt][0], s[nt][1]));
            mx1 = fmaxf(mx1, fmaxf(s[nt][2], s[nt][3]));
        }
        mx0 = fmaxf(mx0, __shfl_xor_sync(0xFFFFFFFFu, mx0, 1));
        mx0 = fmaxf(mx0, __shfl_xor_sync(0xFFFFFFFFu, mx0, 2));
        mx1 = fmaxf(mx1, __shfl_xor_sync(0xFFFFFFFFu, mx1, 1));
        mx1 = fmaxf(mx1, __shfl_xor_sync(0xFFFFFFFFu, mx1, 2));

        const float mn0 = fmaxf(m0v, mx0), mn1 = fmaxf(m1v, mx1);
        const float c0 = ex2(m0v - mn0), c1 = ex2(m1v - mn1);
        l0 *= c0; l1 *= c1;
#pragma unroll
        for (int dt = 0; dt < 8; dt++) {
            o[dt][0] *= c0; o[dt][1] *= c0;
            o[dt][2] *= c1; o[dt][3] *= c1;
        }

        float ls0 = 0.f, ls1 = 0.f;
#pragma unroll
        for (int nt = 0; nt < 8; nt++) {
            const float p0 = ex2(s[nt][0] - mn0);
            const float p1 = ex2(s[nt][1] - mn0);
            const float p2 = ex2(s[nt][2] - mn1);
            const float p3 = ex2(s[nt][3] - mn1);
            ls0 += p0 + p1; ls1 += p2 + p3;
            const int pc = nt * 8 + 2 * tg;
            *(uint2*)&Ps[(wslab + g) * PS_STRIDE + pc] =
                make_uint2(f2tf32(p0), f2tf32(p1));
            *(uint2*)&Ps[(wslab + g + 8) * PS_STRIDE + pc] =
                make_uint2(f2tf32(p2), f2tf32(p3));
        }
        ls0 += __shfl_xor_sync(0xFFFFFFFFu, ls0, 1);
        ls0 += __shfl_xor_sync(0xFFFFFFFFu, ls0, 2);
        ls1 += __shfl_xor_sync(0xFFFFFFFFu, ls1, 1);
        ls1 += __shfl_xor_sync(0xFFFFFFFFu, ls1, 2);
        l0 += ls0; l1 += ls1;
        m0v = mn0; m1v = mn1;

        __syncwarp();   // P stores visible to own-warp loads

        // O += P @ V  (A-frags from Ps, B-frags from Vs)
#pragma unroll
        for (int k8 = 0; k8 < 8; k8++) {
            uint32_t pa[4];
            const int pb = (wslab + g) * PS_STRIDE + k8 * 8 + tg;
            pa[0] = Ps[pb];
            pa[1] = Ps[pb + 8 * PS_STRIDE];
            pa[2] = Ps[pb + 4];
            pa[3] = Ps[pb + 8 * PS_STRIDE + 4];
#pragma unroll
            for (int dt = 0; dt < 8; dt++) {
                const int vb = (k8 * 8 + tg) * VS_STRIDE + dt * 8 + g;
                MMA_TF32(o[dt], pa, Vs[vb], Vs[vb + 4 * VS_STRIDE]);
            }
        }
    }

    const float i0 = 1.f / l0, i1 = 1.f / l1;
    float* Op = O + (size_t)b * SEQ * DMODEL + h * HSZ;
#pragma unroll
    for (int dt = 0; dt < 8; dt++) {
        const int col = dt * 8 + 2 * tg;
        *(float2*)&Op[(size_t)row0 * DMODEL + col] =
            make_float2(o[dt][0] * i0, o[dt][1] * i0);
        *(float2*)&Op[(size_t)row1 * DMODEL + col] =
            make_float2(o[dt][2] * i1, o[dt][3] * i1);
    }
}

// ---------------------------------------------------------------------------
extern "C" void kernel_launch(void* const* d_in, const int* in_sizes, int n_in,
                              void* d_out, int out_size)
{
    const float* queries = (const float*)d_in[0];
    const float* keys    = (const float*)d_in[1];
    const float* values  = (const float*)d_in[2];
    const float* W_Q = (const float*)d_in[3];
    const float* b_Q = (const float*)d_in[4];
    const float* W_K = (const float*)d_in[5];
    const float* b_K = (const float*)d_in[6];
    const float* W_V = (const float*)d_in[7];
    const float* b_V = (const float*)d_in[8];
    const float* W_O = (const float*)d_in[9];
    const float* b_O = (const float*)d_in[10];
    float* out = (float*)d_out;

    float *pQ, *pK, *pV, *pC;
    cudaGetSymbolAddress((void**)&pQ, g_Q);
    cudaGetSymbolAddress((void**)&pK, g_K);
    cudaGetSymbolAddress((void**)&pV, g_V);
    cudaGetSymbolAddress((void**)&pC, g_Ctx);

    dim3 gg(DMODEL / 128, MROWS / 128);   // (6, 64)
    gemm_mma<<<gg, 256>>>(queries, W_Q, b_Q, pQ);
    gemm_mma<<<gg, 256>>>(keys,    W_K, b_K, pK);
    gemm_mma<<<gg, 256>>>(values,  W_V, b_V, pV);

    cudaFuncSetAttribute(attn_mma,
                         cudaFuncAttributeMaxDynamicSharedMemorySize, ATTN_SMEM);
    dim3 ga(SEQ / 64, BATCH * NHEAD);     // (32, 48)
    attn_mma<<<ga, 128, ATTN_SMEM>>>(pQ, pK, pV, pC);

    gemm_mma<<<gg, 256>>>(pC, W_O, b_O, out);
}

// round 4
// speedup vs baseline: 8.5676x; 1.6485x over previous
#include <cuda_runtime.h>
#include <cuda_fp16.h>
#include <cstdint>

#define BATCH  4
#define SEQ    2048
#define DMODEL 768
#define NHEAD  12
#define HSZ    64
#define MROWS  (BATCH*SEQ)

// Scratch (alloc-free rule). All [B,S,D] layout.
__device__ float g_Q  [MROWS*DMODEL];
__device__ float g_K  [MROWS*DMODEL];
__device__ float g_V  [MROWS*DMODEL];
__device__ float g_Ctx[MROWS*DMODEL];

// pack two floats -> f16x2 (lo = first arg)
__device__ __forceinline__ uint32_t pkh2(float lo, float hi) {
    uint32_t d;
    asm("cvt.rn.f16x2.f32 %0, %1, %2;" : "=r"(d) : "f"(hi), "f"(lo));
    return d;
}
__device__ __forceinline__ float ex2(float x) {
    float r; asm("ex2.approx.ftz.f32 %0, %1;" : "=f"(r) : "f"(x)); return r;
}

// D += A(16x16,row) * B(16x8,col)   fp16 in, fp32 accum
#define MMA_F16(d, a, b0v, b1v)                                                \
    asm volatile("mma.sync.aligned.m16n8k16.row.col.f32.f16.f16.f32 "          \
        "{%0,%1,%2,%3}, {%4,%5,%6,%7}, {%8,%9}, {%0,%1,%2,%3};"                \
        : "+f"((d)[0]), "+f"((d)[1]), "+f"((d)[2]), "+f"((d)[3])               \
        : "r"((a)[0]), "r"((a)[1]), "r"((a)[2]), "r"((a)[3]),                  \
          "r"(b0v), "r"(b1v))

// ---------------------------------------------------------------------------
// GEMM: Y[M,N] = X[M,K] @ W[N,K]^T + bias   (fp16 mma, fp32 accum)
// CTA 128x128, 8 warps 2(M)x4(N), warp tile 64x32, K-chunk 32 floats.
// smem tiles: half2 rows, stride 20 words (16 data + 4 pad) ->
// fragment LDS bank = (g*20 + tg) % 32 = 4g+tg+... all 32 lanes distinct.
// ---------------------------------------------------------------------------
#define GS 20

__global__ __launch_bounds__(256)
void gemm_mma(const float* __restrict__ X, const float* __restrict__ W,
              const float* __restrict__ bias, float* __restrict__ Y)
{
    __shared__ uint32_t As[128 * GS];
    __shared__ uint32_t Bs[128 * GS];

    const int tid  = threadIdx.x;
    const int wid  = tid >> 5, lane = tid & 31;
    const int g    = lane >> 2, tg = lane & 3;
    const int m0   = blockIdx.y * 128, n0 = blockIdx.x * 128;
    const int wm   = (wid & 1) * 64;
    const int wn   = (wid >> 1) * 32;
    const int r_ld = tid >> 3;
    const int c_ld = tid & 7;

    float acc[4][4][4] = {};

    float4 ra[4], rb[4];
#pragma unroll
    for (int j = 0; j < 4; j++) {
        const int r = r_ld + j * 32;
        ra[j] = *(const float4*)(X + (size_t)(m0 + r) * DMODEL + c_ld * 4);
        rb[j] = *(const float4*)(W + (size_t)(n0 + r) * DMODEL + c_ld * 4);
    }

    for (int kt = 0; kt < DMODEL / 32; kt++) {
        __syncthreads();
#pragma unroll
        for (int j = 0; j < 4; j++) {
            const int r = r_ld + j * 32;
            *(uint2*)&As[r * GS + c_ld * 2] =
                make_uint2(pkh2(ra[j].x, ra[j].y), pkh2(ra[j].z, ra[j].w));
            *(uint2*)&Bs[r * GS + c_ld * 2] =
                make_uint2(pkh2(rb[j].x, rb[j].y), pkh2(rb[j].z, rb[j].w));
        }
        if (kt + 1 < DMODEL / 32) {
            const int k0 = (kt + 1) * 32;
#pragma unroll
            for (int j = 0; j < 4; j++) {
                const int r = r_ld + j * 32;
                ra[j] = *(const float4*)(X + (size_t)(m0 + r) * DMODEL + k0 + c_ld * 4);
                rb[j] = *(const float4*)(W + (size_t)(n0 + r) * DMODEL + k0 + c_ld * 4);
            }
        }
        __syncthreads();

#pragma unroll
        for (int k16 = 0; k16 < 2; k16++) {
            uint32_t a[4][4], b[4][2];
#pragma unroll
            for (int mt = 0; mt < 4; mt++) {
                const int base = (wm + mt * 16 + g) * GS + k16 * 8 + tg;
                a[mt][0] = As[base];
                a[mt][1] = As[base + 8 * GS];
                a[mt][2] = As[base + 4];
                a[mt][3] = As[base + 8 * GS + 4];
            }
#pragma unroll
            for (int nt = 0; nt < 4; nt++) {
                const int base = (wn + nt * 8 + g) * GS + k16 * 8 + tg;
                b[nt][0] = Bs[base];
                b[nt][1] = Bs[base + 4];
            }
#pragma unroll
            for (int mt = 0; mt < 4; mt++)
#pragma unroll
                for (int nt = 0; nt < 4; nt++)
                    MMA_F16(acc[mt][nt], a[mt], b[nt][0], b[nt][1]);
        }
    }

#pragma unroll
    for (int mt = 0; mt < 4; mt++) {
        const int row = m0 + wm + mt * 16 + g;
#pragma unroll
        for (int nt = 0; nt < 4; nt++) {
            const int col = n0 + wn + nt * 8 + 2 * tg;
            const float b0v = bias[col], b1v = bias[col + 1];
            *(float2*)&Y[(size_t)row * DMODEL + col] =
                make_float2(acc[mt][nt][0] + b0v, acc[mt][nt][1] + b1v);
            *(float2*)&Y[(size_t)(row + 8) * DMODEL + col] =
                make_float2(acc[mt][nt][2] + b0v, acc[mt][nt][3] + b1v);
        }
    }
}

// ---------------------------------------------------------------------------
// fp16 tensor-core causal flash attention. CTA = 128 q rows, 8 warps x 16.
// K tile: half2 rows  Ks[64][36 words]  (bank = 4g+tg, distinct)
// V tile: k-paired    Vp[32][72 words]  Vp[i][d] = {V[2i][d], V[2i+1][d]}
//                                        (bank = 8tg+g, distinct)
// P never touches smem: S-accum layout == A-frag layout (pack with cvt.f16x2).
// ---------------------------------------------------------------------------
#define KSH 36
#define VSH 72

__global__ __launch_bounds__(256)
void attn_mma(const float* __restrict__ Q, const float* __restrict__ K,
              const float* __restrict__ V, float* __restrict__ O)
{
    __shared__ uint32_t Ks[64 * KSH];
    __shared__ uint32_t Vp[32 * VSH];

    const int tid = threadIdx.x, wid = tid >> 5, lane = tid & 31;
    const int g = lane >> 2, tg = lane & 3;
    const int bh = blockIdx.y, b = bh / NHEAD, h = bh % NHEAD;
    const int q0 = blockIdx.x * 128;
    const int wslab = wid * 16;

    const float* Qp = Q + (size_t)b * SEQ * DMODEL + h * HSZ;
    const float* Kp = K + (size_t)b * SEQ * DMODEL + h * HSZ;
    const float* Vs = V + (size_t)b * SEQ * DMODEL + h * HSZ;

    const int row0 = q0 + wslab + g;
    const int row1 = row0 + 8;

    const float qs = 0.125f * 1.44269504f;   // 1/sqrt(64) * log2(e)
    uint32_t qh[4][4];
#pragma unroll
    for (int j = 0; j < 4; j++) {
        const int c = j * 16 + 2 * tg;
        float2 t0 = *(const float2*)(Qp + (size_t)row0 * DMODEL + c);
        float2 t1 = *(const float2*)(Qp + (size_t)row1 * DMODEL + c);
        float2 t2 = *(const float2*)(Qp + (size_t)row0 * DMODEL + c + 8);
        float2 t3 = *(const float2*)(Qp + (size_t)row1 * DMODEL + c + 8);
        qh[j][0] = pkh2(t0.x * qs, t0.y * qs);
        qh[j][1] = pkh2(t1.x * qs, t1.y * qs);
        qh[j][2] = pkh2(t2.x * qs, t2.y * qs);
        qh[j][3] = pkh2(t3.x * qs, t3.y * qs);
    }

    float o[8][4] = {};
    float m0v = -1e30f, m1v = -1e30f, l0 = 0.f, l1 = 0.f;

    for (int kt = 0; kt < q0 + 128; kt += 64) {
        __syncthreads();
        // K tile: 64 rows x 16 float4 = 1024 units
#pragma unroll
        for (int i = tid; i < 1024; i += 256) {
            const int r = i >> 4, c4 = (i & 15) << 2;
            float4 kv = *(const float4*)(Kp + (size_t)(kt + r) * DMODEL + c4);
            *(uint2*)&Ks[r * KSH + (c4 >> 1)] =
                make_uint2(pkh2(kv.x, kv.y), pkh2(kv.z, kv.w));
        }
        // V tile: 32 pair-rows x 16 float4-pairs = 512 units
#pragma unroll
        for (int i = tid; i < 512; i += 256) {
            const int r = i >> 4, c4 = (i & 15) << 2;
            float4 v0 = *(const float4*)(Vs + (size_t)(kt + 2 * r)     * DMODEL + c4);
            float4 v1 = *(const float4*)(Vs + (size_t)(kt + 2 * r + 1) * DMODEL + c4);
            *(uint4*)&Vp[r * VSH + c4] =
                make_uint4(pkh2(v0.x, v1.x), pkh2(v0.y, v1.y),
                           pkh2(v0.z, v1.z), pkh2(v0.w, v1.w));
        }
        __syncthreads();

        if (kt >= q0 + wslab + 16) continue;   // fully above causal diagonal

        // S = Q @ K^T
        float s[8][4] = {};
#pragma unroll
        for (int j = 0; j < 4; j++) {
#pragma unroll
            for (int nt = 0; nt < 8; nt++) {
                const int kb = (nt * 8 + g) * KSH + j * 8 + tg;
                MMA_F16(s[nt], qh[j], Ks[kb], Ks[kb + 4]);
            }
        }

        if (kt + 64 > q0 + wslab) {   // diagonal tile for this warp
#pragma unroll
            for (int nt = 0; nt < 8; nt++) {
                const int cl = kt + nt * 8 + 2 * tg;
                if (cl     > row0) s[nt][0] = -1e30f;
                if (cl + 1 > row0) s[nt][1] = -1e30f;
                if (cl     > row1) s[nt][2] = -1e30f;
                if (cl + 1 > row1) s[nt][3] = -1e30f;
            }
        }

        float mx0 = -1e30f, mx1 = -1e30f;
#pragma unroll
        for (int nt = 0; nt < 8; nt++) {
            mx0 = fmaxf(mx0, fmaxf(s[nt][0], s[nt][1]));
            mx1 = fmaxf(mx1, fmaxf(s[nt][2], s[nt][3]));
        }
        mx0 = fmaxf(mx0, __shfl_xor_sync(0xFFFFFFFFu, mx0, 1));
        mx0 = fmaxf(mx0, __shfl_xor_sync(0xFFFFFFFFu, mx0, 2));
        mx1 = fmaxf(mx1, __shfl_xor_sync(0xFFFFFFFFu, mx1, 1));
        mx1 = fmaxf(mx1, __shfl_xor_sync(0xFFFFFFFFu, mx1, 2));

        const float mn0 = fmaxf(m0v, mx0), mn1 = fmaxf(m1v, mx1);
        const float c0 = ex2(m0v - mn0), c1 = ex2(m1v - mn1);
        l0 *= c0; l1 *= c1;
#pragma unroll
        for (int dt = 0; dt < 8; dt++) {
            o[dt][0] *= c0; o[dt][1] *= c0;
            o[dt][2] *= c1; o[dt][3] *= c1;
        }

        float ls0 = 0.f, ls1 = 0.f;
#pragma unroll
        for (int nt = 0; nt < 8; nt++) {
            s[nt][0] = ex2(s[nt][0] - mn0);
            s[nt][1] = ex2(s[nt][1] - mn0);
            s[nt][2] = ex2(s[nt][2] - mn1);
            s[nt][3] = ex2(s[nt][3] - mn1);
            ls0 += s[nt][0] + s[nt][1];
            ls1 += s[nt][2] + s[nt][3];
        }
        ls0 += __shfl_xor_sync(0xFFFFFFFFu, ls0, 1);
        ls0 += __shfl_xor_sync(0xFFFFFFFFu, ls0, 2);
        ls1 += __shfl_xor_sync(0xFFFFFFFFu, ls1, 1);
        ls1 += __shfl_xor_sync(0xFFFFFFFFu, ls1, 2);
        l0 += ls0; l1 += ls1;
        m0v = mn0; m1v = mn1;

        // O += P @ V   (P A-frags built in registers from S accumulators)
#pragma unroll
        for (int j = 0; j < 4; j++) {
            uint32_t pa[4];
            pa[0] = pkh2(s[2*j  ][0], s[2*j  ][1]);
            pa[1] = pkh2(s[2*j  ][2], s[2*j  ][3]);
            pa[2] = pkh2(s[2*j+1][0], s[2*j+1][1]);
            pa[3] = pkh2(s[2*j+1][2], s[2*j+1][3]);
#pragma unroll
            for (int dt = 0; dt < 8; dt++) {
                const int vb = (j * 8 + tg) * VSH + dt * 8 + g;
                MMA_F16(o[dt], pa, Vp[vb], Vp[vb + 4 * VSH]);
            }
        }
    }

    const float i0 = 1.f / l0, i1 = 1.f / l1;
    float* Op = O + (size_t)b * SEQ * DMODEL + h * HSZ;
#pragma unroll
    for (int dt = 0; dt < 8; dt++) {
        const int col = dt * 8 + 2 * tg;
        *(float2*)&Op[(size_t)row0 * DMODEL + col] =
            make_float2(o[dt][0] * i0, o[dt][1] * i0);
        *(float2*)&Op[(size_t)row1 * DMODEL + col] =
            make_float2(o[dt][2] * i1, o[dt][3] * i1);
    }
}

// ---------------------------------------------------------------------------
extern "C" void kernel_launch(void* const* d_in, const int* in_sizes, int n_in,
                              void* d_out, int out_size)
{
    const float* queries = (const float*)d_in[0];
    const float* keys    = (const float*)d_in[1];
    const float* values  = (const float*)d_in[2];
    const float* W_Q = (const float*)d_in[3];
    const float* b_Q = (const float*)d_in[4];
    const float* W_K = (const float*)d_in[5];
    const float* b_K = (const float*)d_in[6];
    const float* W_V = (const float*)d_in[7];
    const float* b_V = (const float*)d_in[8];
    const float* W_O = (const float*)d_in[9];
    const float* b_O = (const float*)d_in[10];
    float* out = (float*)d_out;

    float *pQ, *pK, *pV, *pC;
    cudaGetSymbolAddress((void**)&pQ, g_Q);
    cudaGetSymbolAddress((void**)&pK, g_K);
    cudaGetSymbolAddress((void**)&pV, g_V);
    cudaGetSymbolAddress((void**)&pC, g_Ctx);

    dim3 gg(DMODEL / 128, MROWS / 128);   // (6, 64)
    gemm_mma<<<gg, 256>>>(queries, W_Q, b_Q, pQ);
    gemm_mma<<<gg, 256>>>(keys,    W_K, b_K, pK);
    gemm_mma<<<gg, 256>>>(values,  W_V, b_V, pV);

    dim3 ga(SEQ / 128, BATCH * NHEAD);    // (16, 48)
    attn_mma<<<ga, 256>>>(pQ, pK, pV, pC);

    gemm_mma<<<gg, 256>>>(pC, W_O, b_O, out);
}

// round 5
// speedup vs baseline: 9.6439x; 1.1256x over previous
#include <cuda_runtime.h>
#include <cuda_fp16.h>
#include <cstdint>

#define BATCH  4
#define SEQ    2048
#define DMODEL 768
#define NHEAD  12
#define HSZ    64
#define MROWS  (BATCH*SEQ)

// Scratch (alloc-free rule). Half precision, [B,S,D] layout.
__device__ __half g_Q  [MROWS*DMODEL];
__device__ __half g_K  [MROWS*DMODEL];
__device__ __half g_V  [MROWS*DMODEL];
__device__ __half g_Ctx[MROWS*DMODEL];

__device__ __forceinline__ uint32_t pkh2(float lo, float hi) {
    uint32_t d;
    asm("cvt.rn.f16x2.f32 %0, %1, %2;" : "=r"(d) : "f"(hi), "f"(lo));
    return d;
}
__device__ __forceinline__ float ex2(float x) {
    float r; asm("ex2.approx.ftz.f32 %0, %1;" : "=f"(r) : "f"(x)); return r;
}
__device__ __forceinline__ uint32_t smem_u32(const void* p) {
    uint32_t a;
    asm("{ .reg .u64 t; cvta.to.shared.u64 t, %1; cvt.u32.u64 %0, t; }"
        : "=r"(a) : "l"(p));
    return a;
}
__device__ __forceinline__ uint32_t prmt(uint32_t a, uint32_t b, uint32_t sel) {
    uint32_t d; asm("prmt.b32 %0,%1,%2,%3;" : "=r"(d) : "r"(a), "r"(b), "r"(sel));
    return d;
}

#define MMA_F16(d, a, b0v, b1v)                                                \
    asm volatile("mma.sync.aligned.m16n8k16.row.col.f32.f16.f16.f32 "          \
        "{%0,%1,%2,%3}, {%4,%5,%6,%7}, {%8,%9}, {%0,%1,%2,%3};"                \
        : "+f"((d)[0]), "+f"((d)[1]), "+f"((d)[2]), "+f"((d)[3])               \
        : "r"((a)[0]), "r"((a)[1]), "r"((a)[2]), "r"((a)[3]),                  \
          "r"(b0v), "r"(b1v))

#define LDSM4(r, addr)                                                         \
    asm volatile("ldmatrix.sync.aligned.m8n8.x4.shared.b16 {%0,%1,%2,%3}, [%4];" \
        : "=r"((r)[0]), "=r"((r)[1]), "=r"((r)[2]), "=r"((r)[3]) : "r"(addr))

// tile-load overloads: produce 2 packed half2 words (4 halves)
__device__ __forceinline__ uint2 ldX(const float* X, size_t off) {
    float4 v = *(const float4*)(X + off);
    return make_uint2(pkh2(v.x, v.y), pkh2(v.z, v.w));
}
__device__ __forceinline__ uint2 ldX(const __half* X, size_t off) {
    return *(const uint2*)(X + off);
}
// epilogue store overloads
__device__ __forceinline__ void stY(float* Y, size_t off, float v0, float v1) {
    *(float2*)(Y + off) = make_float2(v0, v1);
}
__device__ __forceinline__ void stY(__half* Y, size_t off, float v0, float v1) {
    *(uint32_t*)(Y + off) = pkh2(v0, v1);
}

// ---------------------------------------------------------------------------
// GEMM body: Y[M,N] = X[M,K] @ W[N,K]^T + bias   (fp16 mma, fp32 accum)
// CTA 128x128, 8 warps 2(M)x4(N), warp tile 64x32, K-chunk 32.
// Double-buffered smem (one sync per k-iter), ldmatrix fragment loads.
// ---------------------------------------------------------------------------
#define GS 20
#define GBUF (128 * GS)

template<typename XT, typename YT>
__device__ __forceinline__ void gemm_body(
    const XT* __restrict__ X, const float* __restrict__ W,
    const float* __restrict__ bias, YT* __restrict__ Y,
    uint32_t* As, uint32_t* Bs, int m0, int n0)
{
    const int tid  = threadIdx.x;
    const int wid  = tid >> 5, lane = tid & 31;
    const int g    = lane >> 2, tg = lane & 3;
    const int wm   = (wid & 1) * 64;
    const int wn   = (wid >> 1) * 32;
    const int r_ld = tid >> 3;
    const int c_ld = tid & 7;

    float acc[4][4][4] = {};

    uint2 xr[4], wr[4];
#pragma unroll
    for (int j = 0; j < 4; j++) {
        const int r = r_ld + j * 32;
        xr[j] = ldX(X, (size_t)(m0 + r) * DMODEL + c_ld * 4);
        wr[j] = ldX(W, (size_t)(n0 + r) * DMODEL + c_ld * 4);
    }

    const uint32_t aAddr = smem_u32(As) +
        (((wm + (lane & 15)) * GS + (lane >> 4) * 4) << 2);
    const uint32_t bAddr = smem_u32(Bs) +
        (((wn + (lane >> 4) * 8 + (lane & 7)) * GS + ((lane >> 3) & 1) * 4) << 2);

    for (int kt = 0; kt < DMODEL / 32; kt++) {
        const int buf = kt & 1;
        uint32_t* a = As + buf * GBUF;
        uint32_t* bb = Bs + buf * GBUF;
#pragma unroll
        for (int j = 0; j < 4; j++) {
            const int r = r_ld + j * 32;
            *(uint2*)&a [r * GS + c_ld * 2] = xr[j];
            *(uint2*)&bb[r * GS + c_ld * 2] = wr[j];
        }
        if (kt + 1 < DMODEL / 32) {
            const int k0 = (kt + 1) * 32;
#pragma unroll
            for (int j = 0; j < 4; j++) {
                const int r = r_ld + j * 32;
                xr[j] = ldX(X, (size_t)(m0 + r) * DMODEL + k0 + c_ld * 4);
                wr[j] = ldX(W, (size_t)(n0 + r) * DMODEL + k0 + c_ld * 4);
            }
        }
        __syncthreads();

        const uint32_t ao = aAddr + buf * (GBUF * 4);
        const uint32_t bo = bAddr + buf * (GBUF * 4);
#pragma unroll
        for (int k16 = 0; k16 < 2; k16++) {
            uint32_t a4[4][4], b4[2][4];
#pragma unroll
            for (int mt = 0; mt < 4; mt++)
                LDSM4(a4[mt], ao + ((mt * 16 * GS + k16 * 8) << 2));
#pragma unroll
            for (int np = 0; np < 2; np++)
                LDSM4(b4[np], bo + ((np * 16 * GS + k16 * 8) << 2));
#pragma unroll
            for (int mt = 0; mt < 4; mt++)
#pragma unroll
                for (int nt = 0; nt < 4; nt++)
                    MMA_F16(acc[mt][nt], a4[mt],
                            b4[nt >> 1][(nt & 1) * 2], b4[nt >> 1][(nt & 1) * 2 + 1]);
        }
    }

#pragma unroll
    for (int mt = 0; mt < 4; mt++) {
        const int row = m0 + wm + mt * 16 + g;
#pragma unroll
        for (int nt = 0; nt < 4; nt++) {
            const int col = n0 + wn + nt * 8 + 2 * tg;
            const float b0v = bias[col], b1v = bias[col + 1];
            stY(Y, (size_t)row * DMODEL + col,       acc[mt][nt][0] + b0v, acc[mt][nt][1] + b1v);
            stY(Y, (size_t)(row + 8) * DMODEL + col, acc[mt][nt][2] + b0v, acc[mt][nt][3] + b1v);
        }
    }
}

// fused QKV projection (blockIdx.z selects matrix)
__global__ __launch_bounds__(256)
void gemm_qkv(const float* __restrict__ Xq, const float* __restrict__ Xk,
              const float* __restrict__ Xv,
              const float* __restrict__ WQ, const float* __restrict__ bQ,
              const float* __restrict__ WK, const float* __restrict__ bK,
              const float* __restrict__ WV, const float* __restrict__ bV,
              __half* __restrict__ Q, __half* __restrict__ K, __half* __restrict__ V)
{
    __shared__ uint32_t As[2 * GBUF];
    __shared__ uint32_t Bs[2 * GBUF];
    const int m0 = blockIdx.y * 128, n0 = blockIdx.x * 128;
    if (blockIdx.z == 0)      gemm_body(Xq, WQ, bQ, Q, As, Bs, m0, n0);
    else if (blockIdx.z == 1) gemm_body(Xk, WK, bK, K, As, Bs, m0, n0);
    else                      gemm_body(Xv, WV, bV, V, As, Bs, m0, n0);
}

__global__ __launch_bounds__(256)
void gemm_out(const __half* __restrict__ X, const float* __restrict__ W,
              const float* __restrict__ bias, float* __restrict__ Y)
{
    __shared__ uint32_t As[2 * GBUF];
    __shared__ uint32_t Bs[2 * GBUF];
    gemm_body(X, W, bias, Y, As, Bs, blockIdx.y * 128, blockIdx.x * 128);
}

// ---------------------------------------------------------------------------
// fp16 flash attention. CTA = 128 q rows, 8 warps x 16.
// K tile: half rows   Ks[2][64][36 words]   (straight uint4 copy)
// V tile: k-paired    Vp[2][32][72 words]   (prmt interleave)
// Double-buffered, one sync per tile. P stays in registers.
// ---------------------------------------------------------------------------
#define KSH 36
#define VSH 72
#define KBUF (64 * KSH)
#define VBUF (32 * VSH)

__global__ __launch_bounds__(256)
void attn_mma(const __half* __restrict__ Q, const __half* __restrict__ K,
              const __half* __restrict__ V, __half* __restrict__ O)
{
    __shared__ uint32_t Ks[2 * KBUF];
    __shared__ uint32_t Vp[2 * VBUF];

    const int tid = threadIdx.x, wid = tid >> 5, lane = tid & 31;
    const int g = lane >> 2, tg = lane & 3;
    const int bh = blockIdx.y, b = bh / NHEAD, h = bh % NHEAD;
    const int q0 = ((int)gridDim.x - 1 - (int)blockIdx.x) * 128;  // heavy first
    const int wslab = wid * 16;

    const __half* Qp = Q + (size_t)b * SEQ * DMODEL + h * HSZ;
    const __half* Kp = K + (size_t)b * SEQ * DMODEL + h * HSZ;
    const __half* Vs = V + (size_t)b * SEQ * DMODEL + h * HSZ;

    const int row0 = q0 + wslab + g;
    const int row1 = row0 + 8;

    // raw Q fragments (scale folded into softmax exponent)
    uint32_t qh[4][4];
    {
        const __half* Qr0 = Qp + (size_t)row0 * DMODEL;
        const __half* Qr1 = Qp + (size_t)row1 * DMODEL;
#pragma unroll
        for (int j = 0; j < 4; j++) {
            const int c = j * 16 + 2 * tg;
            qh[j][0] = *(const uint32_t*)(Qr0 + c);
            qh[j][1] = *(const uint32_t*)(Qr1 + c);
            qh[j][2] = *(const uint32_t*)(Qr0 + c + 8);
            qh[j][3] = *(const uint32_t*)(Qr1 + c + 8);
        }
    }

    const uint32_t kAddr = smem_u32(Ks) +
        ((((lane >> 4) * 8 + (lane & 7)) * KSH + ((lane >> 3) & 1) * 4) << 2);

    float o[8][4] = {};
    float m0v = -1e30f, m1v = -1e30f, l0 = 0.f, l1 = 0.f;
    const float qs2 = 0.125f * 1.44269504f;   // 1/sqrt(64) * log2(e)

    for (int kt = 0; kt < q0 + 128; kt += 64) {
        const int buf = (kt >> 6) & 1;
        // K tile: 64 rows x 32 words, uint4 chunks
        {
            uint32_t* kd = Ks + buf * KBUF;
#pragma unroll
            for (int i = tid; i < 512; i += 256) {
                const int r = i >> 3, c8 = (i & 7) * 8;      // 8 halves
                uint4 kv = *(const uint4*)(Kp + (size_t)(kt + r) * DMODEL + c8);
                *(uint4*)&kd[r * KSH + (c8 >> 1)] = kv;
            }
            // V tile: pair-interleave rows 2r,2r+1
            uint32_t* vd = Vp + buf * VBUF;
#pragma unroll
            for (int i = tid; i < 512; i += 256) {
                const int r = i >> 4, d4 = (i & 15) * 4;     // 4 d-halves
                uint2 v0 = *(const uint2*)(Vs + (size_t)(kt + 2 * r)     * DMODEL + d4);
                uint2 v1 = *(const uint2*)(Vs + (size_t)(kt + 2 * r + 1) * DMODEL + d4);
                *(uint4*)&vd[r * VSH + d4] =
                    make_uint4(prmt(v0.x, v1.x, 0x5410), prmt(v0.x, v1.x, 0x7632),
                               prmt(v0.y, v1.y, 0x5410), prmt(v0.y, v1.y, 0x7632));
            }
        }
        __syncthreads();

        if (kt >= q0 + wslab + 16) continue;   // fully above causal diagonal

        // S = Q @ K^T
        float s[8][4] = {};
        const uint32_t ko = kAddr + buf * (KBUF * 4);
#pragma unroll
        for (int j = 0; j < 4; j++) {
            uint32_t kb[4][4];
#pragma unroll
            for (int np = 0; np < 4; np++)
                LDSM4(kb[np], ko + ((np * 16 * KSH + j * 8) << 2));
#pragma unroll
            for (int nt = 0; nt < 8; nt++)
                MMA_F16(s[nt], qh[j],
                        kb[nt >> 1][(nt & 1) * 2], kb[nt >> 1][(nt & 1) * 2 + 1]);
        }

        if (kt + 64 > q0 + wslab) {   // diagonal tile for this warp
#pragma unroll
            for (int nt = 0; nt < 8; nt++) {
                const int cl = kt + nt * 8 + 2 * tg;
                if (cl     > row0) s[nt][0] = -1e30f;
                if (cl + 1 > row0) s[nt][1] = -1e30f;
                if (cl     > row1) s[nt][2] = -1e30f;
                if (cl + 1 > row1) s[nt][3] = -1e30f;
            }
        }

        float mx0 = -1e30f, mx1 = -1e30f;
#pragma unroll
        for (int nt = 0; nt < 8; nt++) {
            mx0 = fmaxf(mx0, fmaxf(s[nt][0], s[nt][1]));
            mx1 = fmaxf(mx1, fmaxf(s[nt][2], s[nt][3]));
        }
        mx0 = fmaxf(mx0, __shfl_xor_sync(0xFFFFFFFFu, mx0, 1));
        mx0 = fmaxf(mx0, __shfl_xor_sync(0xFFFFFFFFu, mx0, 2));
        mx1 = fmaxf(mx1, __shfl_xor_sync(0xFFFFFFFFu, mx1, 1));
        mx1 = fmaxf(mx1, __shfl_xor_sync(0xFFFFFFFFu, mx1, 2));

        const float mn0 = fmaxf(m0v, mx0), mn1 = fmaxf(m1v, mx1);
        const float c0 = ex2((m0v - mn0) * qs2), c1 = ex2((m1v - mn1) * qs2);
        l0 *= c0; l1 *= c1;
#pragma unroll
        for (int dt = 0; dt < 8; dt++) {
            o[dt][0] *= c0; o[dt][1] *= c0;
            o[dt][2] *= c1; o[dt][3] *= c1;
        }

        const float mq0 = mn0 * qs2, mq1 = mn1 * qs2;
        float ls0 = 0.f, ls1 = 0.f;
#pragma unroll
        for (int nt = 0; nt < 8; nt++) {
            s[nt][0] = ex2(s[nt][0] * qs2 - mq0);
            s[nt][1] = ex2(s[nt][1] * qs2 - mq0);
            s[nt][2] = ex2(s[nt][2] * qs2 - mq1);
            s[nt][3] = ex2(s[nt][3] * qs2 - mq1);
            ls0 += s[nt][0] + s[nt][1];
            ls1 += s[nt][2] + s[nt][3];
        }
        ls0 += __shfl_xor_sync(0xFFFFFFFFu, ls0, 1);
        ls0 += __shfl_xor_sync(0xFFFFFFFFu, ls0, 2);
        ls1 += __shfl_xor_sync(0xFFFFFFFFu, ls1, 1);
        ls1 += __shfl_xor_sync(0xFFFFFFFFu, ls1, 2);
        l0 += ls0; l1 += ls1;
        m0v = mn0; m1v = mn1;

        // O += P @ V   (P fragments built in registers)
        const uint32_t* vbuf = Vp + buf * VBUF;
#pragma unroll
        for (int j = 0; j < 4; j++) {
            uint32_t pa[4];
            pa[0] = pkh2(s[2*j  ][0], s[2*j  ][1]);
            pa[1] = pkh2(s[2*j  ][2], s[2*j  ][3]);
            pa[2] = pkh2(s[2*j+1][0], s[2*j+1][1]);
            pa[3] = pkh2(s[2*j+1][2], s[2*j+1][3]);
#pragma unroll
            for (int dt = 0; dt < 8; dt++) {
                const int vb = (j * 8 + tg) * VSH + dt * 8 + g;
                MMA_F16(o[dt], pa, vbuf[vb], vbuf[vb + 4 * VSH]);
            }
        }
    }

    const float i0 = 1.f / l0, i1 = 1.f / l1;
    __half* Op = O + (size_t)b * SEQ * DMODEL + h * HSZ;
#pragma unroll
    for (int dt = 0; dt < 8; dt++) {
        const int col = dt * 8 + 2 * tg;
        *(uint32_t*)(Op + (size_t)row0 * DMODEL + col) = pkh2(o[dt][0] * i0, o[dt][1] * i0);
        *(uint32_t*)(Op + (size_t)row1 * DMODEL + col) = pkh2(o[dt][2] * i1, o[dt][3] * i1);
    }
}

// ---------------------------------------------------------------------------
extern "C" void kernel_launch(void* const* d_in, const int* in_sizes, int n_in,
                              void* d_out, int out_size)
{
    const float* queries = (const float*)d_in[0];
    const float* keys    = (const float*)d_in[1];
    const float* values  = (const float*)d_in[2];
    const float* W_Q = (const float*)d_in[3];
    const float* b_Q = (const float*)d_in[4];
    const float* W_K = (const float*)d_in[5];
    const float* b_K = (const float*)d_in[6];
    const float* W_V = (const float*)d_in[7];
    const float* b_V = (const float*)d_in[8];
    const float* W_O = (const float*)d_in[9];
    const float* b_O = (const float*)d_in[10];
    float* out = (float*)d_out;

    __half *pQ, *pK, *pV, *pC;
    cudaGetSymbolAddress((void**)&pQ, g_Q);
    cudaGetSymbolAddress((void**)&pK, g_K);
    cudaGetSymbolAddress((void**)&pV, g_V);
    cudaGetSymbolAddress((void**)&pC, g_Ctx);

    dim3 g3(DMODEL / 128, MROWS / 128, 3);   // (6, 64, 3)
    gemm_qkv<<<g3, 256>>>(queries, keys, values,
                          W_Q, b_Q, W_K, b_K, W_V, b_V, pQ, pK, pV);

    dim3 ga(SEQ / 128, BATCH * NHEAD);       // (16, 48)
    attn_mma<<<ga, 256>>>(pQ, pK, pV, pC);

    dim3 gg(DMODEL / 128, MROWS / 128);      // (6, 64)
    gemm_out<<<gg, 256>>>(pC, W_O, b_O, out);
}

// round 6
// speedup vs baseline: 10.2622x; 1.0641x over previous
#include <cuda_runtime.h>
#include <cuda_fp16.h>
#include <cstdint>

#define BATCH  4
#define SEQ    2048
#define DMODEL 768
#define NHEAD  12
#define HSZ    64
#define MROWS  (BATCH*SEQ)

// Scratch (alloc-free rule). Half precision everywhere.
__device__ __half g_hX[3][MROWS*DMODEL];     // converted queries/keys/values
__device__ __half g_hW[4][DMODEL*DMODEL];    // converted W_Q/W_K/W_V/W_O
__device__ __half g_Q  [MROWS*DMODEL];
__device__ __half g_K  [MROWS*DMODEL];
__device__ __half g_V  [MROWS*DMODEL];
__device__ __half g_Ctx[MROWS*DMODEL];

__device__ __forceinline__ uint32_t pkh2(float lo, float hi) {
    uint32_t d;
    asm("cvt.rn.f16x2.f32 %0, %1, %2;" : "=r"(d) : "f"(hi), "f"(lo));
    return d;
}
__device__ __forceinline__ float ex2(float x) {
    float r; asm("ex2.approx.ftz.f32 %0, %1;" : "=f"(r) : "f"(x)); return r;
}
__device__ __forceinline__ uint32_t smem_u32(const void* p) {
    uint32_t a;
    asm("{ .reg .u64 t; cvta.to.shared.u64 t, %1; cvt.u32.u64 %0, t; }"
        : "=r"(a) : "l"(p));
    return a;
}

#define MMA_F16(d, a, b0v, b1v)                                                \
    asm volatile("mma.sync.aligned.m16n8k16.row.col.f32.f16.f16.f32 "          \
        "{%0,%1,%2,%3}, {%4,%5,%6,%7}, {%8,%9}, {%0,%1,%2,%3};"                \
        : "+f"((d)[0]), "+f"((d)[1]), "+f"((d)[2]), "+f"((d)[3])               \
        : "r"((a)[0]), "r"((a)[1]), "r"((a)[2]), "r"((a)[3]),                  \
          "r"(b0v), "r"(b1v))

#define LDSM4(r, addr)                                                         \
    asm volatile("ldmatrix.sync.aligned.m8n8.x4.shared.b16 {%0,%1,%2,%3}, [%4];" \
        : "=r"((r)[0]), "=r"((r)[1]), "=r"((r)[2]), "=r"((r)[3]) : "r"(addr))
#define LDSM4T(r, addr)                                                        \
    asm volatile("ldmatrix.sync.aligned.m8n8.x4.trans.shared.b16 {%0,%1,%2,%3}, [%4];" \
        : "=r"((r)[0]), "=r"((r)[1]), "=r"((r)[2]), "=r"((r)[3]) : "r"(addr))

#define CP16(dst, src)                                                         \
    asm volatile("cp.async.cg.shared.global [%0], [%1], 16;" :: "r"(dst), "l"(src))
#define CP_COMMIT() asm volatile("cp.async.commit_group;" ::: "memory")
#define CP_WAIT(n)  asm volatile("cp.async.wait_group %0;" :: "n"(n) : "memory")

// ---------------------------------------------------------------------------
// fp32 -> fp16 conversion, 7 tensors in one launch (grid.y selects tensor)
// ---------------------------------------------------------------------------
struct Cvt7 { const float* s[7]; __half* d[7]; int n4[7]; };

__global__ __launch_bounds__(256)
void convert_k(Cvt7 c) {
    const int y = blockIdx.y;
    const float4* s = (const float4*)c.s[y];
    uint2* d = (uint2*)c.d[y];
    const int n4 = c.n4[y];
    for (int i = blockIdx.x * 256 + threadIdx.x; i < n4; i += gridDim.x * 256) {
        float4 v = s[i];
        d[i] = make_uint2(pkh2(v.x, v.y), pkh2(v.z, v.w));
    }
}

// ---------------------------------------------------------------------------
// GEMM: Y[M,N] = X[M,K] @ W[N,K]^T + bias  (half in, fp32 accum)
// CTA 128x128, 8 warps 2(M)x4(N), warp 64x32, k-chunk 32, 4-stage cp.async.
// smem row stride GS=20 words (16 data + 4 pad): conflict-free ldmatrix.
// ---------------------------------------------------------------------------
#define GS   20
#define GBUF (128 * GS)
#define GEMM_SMEM (4 * 2 * GBUF * 4)    // 81920 B

__device__ __forceinline__ void stY(float* Y, size_t off, float v0, float v1) {
    *(float2*)(Y + off) = make_float2(v0, v1);
}
__device__ __forceinline__ void stY(__half* Y, size_t off, float v0, float v1) {
    *(uint32_t*)(Y + off) = pkh2(v0, v1);
}

template<typename YT>
__device__ __forceinline__ void gemm_body(
    const __half* __restrict__ X, const __half* __restrict__ W,
    const float* __restrict__ bias, YT* __restrict__ Y, int m0, int n0)
{
    extern __shared__ uint32_t dsm[];
    const uint32_t sbase = smem_u32(dsm);
    const int tid = threadIdx.x, lane = tid & 31, wid = tid >> 5;
    const int g = lane >> 2, tg = lane & 3;
    const int wm = (wid & 1) * 64, wn = (wid >> 1) * 32;

    const __half* Xb = X + (size_t)m0 * DMODEL;
    const __half* Wb = W + (size_t)n0 * DMODEL;
    const int r0 = tid >> 2, c0 = tid & 3;   // 16B-chunk mapping

    float acc[4][4][4] = {};

#define G_ISSUE(kt, s) do {                                                    \
        uint32_t ab = sbase + (s) * 2 * GBUF * 4;                              \
        uint32_t bb = ab + GBUF * 4;                                           \
        _Pragma("unroll")                                                      \
        for (int j = 0; j < 2; j++) {                                          \
            const int r = r0 + j * 64;                                         \
            const uint32_t off = (uint32_t)(r * GS + c0 * 4) << 2;             \
            CP16(ab + off, Xb + (size_t)r * DMODEL + (kt) * 32 + c0 * 8);      \
            CP16(bb + off, Wb + (size_t)r * DMODEL + (kt) * 32 + c0 * 8);      \
        } } while (0)

    G_ISSUE(0, 0); CP_COMMIT();
    G_ISSUE(1, 1); CP_COMMIT();
    G_ISSUE(2, 2); CP_COMMIT();

    const uint32_t aF = (uint32_t)((wm + (lane & 15)) * GS + (lane >> 4) * 4) << 2;
    const uint32_t bF = (uint32_t)((wn + (lane >> 4) * 8 + (lane & 7)) * GS
                                   + ((lane >> 3) & 1) * 4) << 2;

    const int NK = DMODEL / 32;   // 24
    for (int kt = 0; kt < NK; kt++) {
        CP_WAIT(2);
        __syncthreads();
        if (kt + 3 < NK) G_ISSUE(kt + 3, (kt + 3) & 3);
        CP_COMMIT();

        const uint32_t sb2 = sbase + (kt & 3) * 2 * GBUF * 4;
        const uint32_t ao = sb2 + aF;
        const uint32_t bo = sb2 + GBUF * 4 + bF;
#pragma unroll
        for (int k16 = 0; k16 < 2; k16++) {
            uint32_t a4[4][4], b4[2][4];
#pragma unroll
            for (int mt = 0; mt < 4; mt++)
                LDSM4(a4[mt], ao + (uint32_t)((mt * 16 * GS + k16 * 8) << 2));
#pragma unroll
            for (int np = 0; np < 2; np++)
                LDSM4(b4[np], bo + (uint32_t)((np * 16 * GS + k16 * 8) << 2));
#pragma unroll
            for (int mt = 0; mt < 4; mt++)
#pragma unroll
                for (int nt = 0; nt < 4; nt++)
                    MMA_F16(acc[mt][nt], a4[mt],
                            b4[nt >> 1][(nt & 1) * 2], b4[nt >> 1][(nt & 1) * 2 + 1]);
        }
    }
#undef G_ISSUE

#pragma unroll
    for (int mt = 0; mt < 4; mt++) {
        const int row = m0 + wm + mt * 16 + g;
#pragma unroll
        for (int nt = 0; nt < 4; nt++) {
            const int col = n0 + wn + nt * 8 + 2 * tg;
            const float b0v = bias[col], b1v = bias[col + 1];
            stY(Y, (size_t)row * DMODEL + col,       acc[mt][nt][0] + b0v, acc[mt][nt][1] + b1v);
            stY(Y, (size_t)(row + 8) * DMODEL + col, acc[mt][nt][2] + b0v, acc[mt][nt][3] + b1v);
        }
    }
}

__global__ __launch_bounds__(256)
void gemm_qkv(const __half* __restrict__ X0, const __half* __restrict__ X1,
              const __half* __restrict__ X2,
              const __half* __restrict__ W0, const float* __restrict__ b0p,
              const __half* __restrict__ W1, const float* __restrict__ b1p,
              const __half* __restrict__ W2, const float* __restrict__ b2p,
              __half* __restrict__ Q, __half* __restrict__ K, __half* __restrict__ V)
{
    const int m0 = blockIdx.y * 128, n0 = blockIdx.x * 128;
    if (blockIdx.z == 0)      gemm_body(X0, W0, b0p, Q, m0, n0);
    else if (blockIdx.z == 1) gemm_body(X1, W1, b1p, K, m0, n0);
    else                      gemm_body(X2, W2, b2p, V, m0, n0);
}

__global__ __launch_bounds__(256)
void gemm_out(const __half* __restrict__ X, const __half* __restrict__ W,
              const float* __restrict__ bias, float* __restrict__ Y)
{
    gemm_body(X, W, bias, Y, blockIdx.y * 128, blockIdx.x * 128);
}

// ---------------------------------------------------------------------------
// fp16 flash attention. CTA = 128 q rows, 8 warps x 16. 3-stage cp.async
// K/V tiles (64 rows x 64 halves, stride 36 words). V frags via ldmatrix.trans.
// ---------------------------------------------------------------------------
#define ASH  36
#define ABUF (64 * ASH)
#define ATTN_SMEM (3 * 2 * ABUF * 4)    // 55296 B

__global__ __launch_bounds__(256)
void attn_mma(const __half* __restrict__ Q, const __half* __restrict__ K,
              const __half* __restrict__ V, __half* __restrict__ O)
{
    extern __shared__ uint32_t dsm[];
    const uint32_t sbase = smem_u32(dsm);

    const int tid = threadIdx.x, wid = tid >> 5, lane = tid & 31;
    const int g = lane >> 2, tg = lane & 3;
    const int bh = blockIdx.y, b = bh / NHEAD, h = bh % NHEAD;
    const int q0 = ((int)gridDim.x - 1 - (int)blockIdx.x) * 128;  // heavy first
    const int wslab = wid * 16;

    const __half* Qg = Q + (size_t)b * SEQ * DMODEL + h * HSZ;
    const __half* Kg = K + (size_t)b * SEQ * DMODEL + h * HSZ;
    const __half* Vg = V + (size_t)b * SEQ * DMODEL + h * HSZ;

    const int row0 = q0 + wslab + g;
    const int row1 = row0 + 8;

    uint32_t qh[4][4];
    {
        const __half* Qr0 = Qg + (size_t)row0 * DMODEL;
        const __half* Qr1 = Qg + (size_t)row1 * DMODEL;
#pragma unroll
        for (int j = 0; j < 4; j++) {
            const int c = j * 16 + 2 * tg;
            qh[j][0] = *(const uint32_t*)(Qr0 + c);
            qh[j][1] = *(const uint32_t*)(Qr1 + c);
            qh[j][2] = *(const uint32_t*)(Qr0 + c + 8);
            qh[j][3] = *(const uint32_t*)(Qr1 + c + 8);
        }
    }

    const int ar0 = tid >> 3, ac0 = tid & 7;   // 16B-chunk mapping

#define A_ISSUE(kt, s) do {                                                    \
        uint32_t kb = sbase + (s) * 2 * ABUF * 4;                              \
        uint32_t vb = kb + ABUF * 4;                                           \
        _Pragma("unroll")                                                      \
        for (int j = 0; j < 2; j++) {                                          \
            const int r = ar0 + j * 32;                                        \
            const uint32_t off = (uint32_t)(r * ASH + ac0 * 4) << 2;           \
            CP16(kb + off, Kg + (size_t)((kt) + r) * DMODEL + ac0 * 8);        \
            CP16(vb + off, Vg + (size_t)((kt) + r) * DMODEL + ac0 * 8);        \
        } } while (0)

    const uint32_t kF = (uint32_t)(((lane >> 4) * 8 + (lane & 7)) * ASH
                                   + ((lane >> 3) & 1) * 4) << 2;
    const uint32_t vF = (uint32_t)((((lane >> 3) & 1) * 8 + (lane & 7)) * ASH
                                   + (lane >> 4) * 4) << 2;

    float o[8][4] = {};
    float m0v = -1e30f, m1v = -1e30f, l0 = 0.f, l1 = 0.f;
    const float qs2 = 0.125f * 1.44269504f;

    const int ntiles = q0 / 64 + 2;
    A_ISSUE(0, 0);  CP_COMMIT();
    A_ISSUE(64, 1); CP_COMMIT();

    for (int t = 0; t < ntiles; t++) {
        const int kt = t * 64;
        CP_WAIT(1);
        __syncthreads();
        if (t + 2 < ntiles) A_ISSUE((t + 2) * 64, (t + 2) % 3);
        CP_COMMIT();

        if (kt >= q0 + wslab + 16) continue;   // compute-only skip

        const uint32_t sb2 = sbase + (t % 3) * 2 * ABUF * 4;
        const uint32_t ko = sb2 + kF;
        const uint32_t vo = sb2 + ABUF * 4 + vF;

        // S = Q @ K^T
        float s[8][4] = {};
#pragma unroll
        for (int j = 0; j < 4; j++) {
            uint32_t kb4[4][4];
#pragma unroll
            for (int np = 0; np < 4; np++)
                LDSM4(kb4[np], ko + (uint32_t)((np * 16 * ASH + j * 8) << 2));
#pragma unroll
            for (int nt = 0; nt < 8; nt++)
                MMA_F16(s[nt], qh[j],
                        kb4[nt >> 1][(nt & 1) * 2], kb4[nt >> 1][(nt & 1) * 2 + 1]);
        }

        if (kt + 64 > q0 + wslab) {   // diagonal tile for this warp
#pragma unroll
            for (int nt = 0; nt < 8; nt++) {
                const int cl = kt + nt * 8 + 2 * tg;
                if (cl     > row0) s[nt][0] = -1e30f;
                if (cl + 1 > row0) s[nt][1] = -1e30f;
                if (cl     > row1) s[nt][2] = -1e30f;
                if (cl + 1 > row1) s[nt][3] = -1e30f;
            }
        }

        float mx0 = -1e30f, mx1 = -1e30f;
#pragma unroll
        for (int nt = 0; nt < 8; nt++) {
            mx0 = fmaxf(mx0, fmaxf(s[nt][0], s[nt][1]));
            mx1 = fmaxf(mx1, fmaxf(s[nt][2], s[nt][3]));
        }
        mx0 = fmaxf(mx0, __shfl_xor_sync(0xFFFFFFFFu, mx0, 1));
        mx0 = fmaxf(mx0, __shfl_xor_sync(0xFFFFFFFFu, mx0, 2));
        mx1 = fmaxf(mx1, __shfl_xor_sync(0xFFFFFFFFu, mx1, 1));
        mx1 = fmaxf(mx1, __shfl_xor_sync(0xFFFFFFFFu, mx1, 2));

        const float mn0 = fmaxf(m0v, mx0), mn1 = fmaxf(m1v, mx1);
        const float c0 = ex2((m0v - mn0) * qs2), c1 = ex2((m1v - mn1) * qs2);
        l0 *= c0; l1 *= c1;
#pragma unroll
        for (int dt = 0; dt < 8; dt++) {
            o[dt][0] *= c0; o[dt][1] *= c0;
            o[dt][2] *= c1; o[dt][3] *= c1;
        }

        const float mq0 = mn0 * qs2, mq1 = mn1 * qs2;
        float ls0 = 0.f, ls1 = 0.f;
#pragma unroll
        for (int nt = 0; nt < 8; nt++) {
            s[nt][0] = ex2(s[nt][0] * qs2 - mq0);
            s[nt][1] = ex2(s[nt][1] * qs2 - mq0);
            s[nt][2] = ex2(s[nt][2] * qs2 - mq1);
            s[nt][3] = ex2(s[nt][3] * qs2 - mq1);
            ls0 += s[nt][0] + s[nt][1];
            ls1 += s[nt][2] + s[nt][3];
        }
        ls0 += __shfl_xor_sync(0xFFFFFFFFu, ls0, 1);
        ls0 += __shfl_xor_sync(0xFFFFFFFFu, ls0, 2);
        ls1 += __shfl_xor_sync(0xFFFFFFFFu, ls1, 1);
        ls1 += __shfl_xor_sync(0xFFFFFFFFu, ls1, 2);
        l0 += ls0; l1 += ls1;
        m0v = mn0; m1v = mn1;

        // O += P @ V   (P in registers; V B-frags via ldmatrix.trans)
#pragma unroll
        for (int j = 0; j < 4; j++) {
            uint32_t pa[4];
            pa[0] = pkh2(s[2*j  ][0], s[2*j  ][1]);
            pa[1] = pkh2(s[2*j  ][2], s[2*j  ][3]);
            pa[2] = pkh2(s[2*j+1][0], s[2*j+1][1]);
            pa[3] = pkh2(s[2*j+1][2], s[2*j+1][3]);
#pragma unroll
            for (int dtp = 0; dtp < 4; dtp++) {
                uint32_t vb4[4];
                LDSM4T(vb4, vo + (uint32_t)((j * 16 * ASH + dtp * 8) << 2));
                MMA_F16(o[2*dtp    ], pa, vb4[0], vb4[1]);
                MMA_F16(o[2*dtp + 1], pa, vb4[2], vb4[3]);
            }
        }
    }
#undef A_ISSUE

    const float i0 = 1.f / l0, i1 = 1.f / l1;
    __half* Op = O + (size_t)b * SEQ * DMODEL + h * HSZ;
#pragma unroll
    for (int dt = 0; dt < 8; dt++) {
        const int col = dt * 8 + 2 * tg;
        *(uint32_t*)(Op + (size_t)row0 * DMODEL + col) = pkh2(o[dt][0] * i0, o[dt][1] * i0);
        *(uint32_t*)(Op + (size_t)row1 * DMODEL + col) = pkh2(o[dt][2] * i1, o[dt][3] * i1);
    }
}

// ---------------------------------------------------------------------------
extern "C" void kernel_launch(void* const* d_in, const int* in_sizes, int n_in,
                              void* d_out, int out_size)
{
    const float* queries = (const float*)d_in[0];
    const float* keys    = (const float*)d_in[1];
    const float* values  = (const float*)d_in[2];
    const float* W_Q = (const float*)d_in[3];
    const float* b_Q = (const float*)d_in[4];
    const float* W_K = (const float*)d_in[5];
    const float* b_K = (const float*)d_in[6];
    const float* W_V = (const float*)d_in[7];
    const float* b_V = (const float*)d_in[8];
    const float* W_O = (const float*)d_in[9];
    const float* b_O = (const float*)d_in[10];
    float* out = (float*)d_out;

    __half *hX, *hW, *pQ, *pK, *pV, *pC;
    cudaGetSymbolAddress((void**)&hX, g_hX);
    cudaGetSymbolAddress((void**)&hW, g_hW);
    cudaGetSymbolAddress((void**)&pQ, g_Q);
    cudaGetSymbolAddress((void**)&pK, g_K);
    cudaGetSymbolAddress((void**)&pV, g_V);
    cudaGetSymbolAddress((void**)&pC, g_Ctx);

    __half* hXq = hX;
    __half* hXk = hX + (size_t)MROWS * DMODEL;
    __half* hXv = hX + 2 * (size_t)MROWS * DMODEL;
    __half* hWQ = hW;
    __half* hWK = hW + (size_t)DMODEL * DMODEL;
    __half* hWV = hW + 2 * (size_t)DMODEL * DMODEL;
    __half* hWO = hW + 3 * (size_t)DMODEL * DMODEL;

    Cvt7 c;
    c.s[0] = queries; c.d[0] = hXq; c.n4[0] = MROWS * DMODEL / 4;
    c.s[1] = keys;    c.d[1] = hXk; c.n4[1] = MROWS * DMODEL / 4;
    c.s[2] = values;  c.d[2] = hXv; c.n4[2] = MROWS * DMODEL / 4;
    c.s[3] = W_Q;     c.d[3] = hWQ; c.n4[3] = DMODEL * DMODEL / 4;
    c.s[4] = W_K;     c.d[4] = hWK; c.n4[4] = DMODEL * DMODEL / 4;
    c.s[5] = W_V;     c.d[5] = hWV; c.n4[5] = DMODEL * DMODEL / 4;
    c.s[6] = W_O;     c.d[6] = hWO; c.n4[6] = DMODEL * DMODEL / 4;
    dim3 gc(MROWS * DMODEL / 4 / 256 / 6, 7);   // (4096, 7) grid-stride
    convert_k<<<gc, 256>>>(c);

    cudaFuncSetAttribute(gemm_qkv, cudaFuncAttributeMaxDynamicSharedMemorySize, GEMM_SMEM);
    cudaFuncSetAttribute(gemm_out, cudaFuncAttributeMaxDynamicSharedMemorySize, GEMM_SMEM);
    cudaFuncSetAttribute(attn_mma, cudaFuncAttributeMaxDynamicSharedMemorySize, ATTN_SMEM);

    dim3 g3(DMODEL / 128, MROWS / 128, 3);   // (6, 64, 3)
    gemm_qkv<<<g3, 256, GEMM_SMEM>>>(hXq, hXk, hXv,
                                     hWQ, b_Q, hWK, b_K, hWV, b_V, pQ, pK, pV);

    dim3 ga(SEQ / 128, BATCH * NHEAD);       // (16, 48)
    attn_mma<<<ga, 256, ATTN_SMEM>>>(pQ, pK, pV, pC);

    dim3 gg(DMODEL / 128, MROWS / 128);      // (6, 64)
    gemm_out<<<gg, 256, GEMM_SMEM>>>(pC, hWO, b_O, out);
}